// round 12
// baseline (speedup 1.0000x reference)
#include <cuda_runtime.h>
#include <math.h>

#define BATCH 8
#define NCLS 80
#define POOL 3320           // 1000+1000+1000+256+64
#define NPAD 4096
#define SCR_STRIDE 21504    // 16384+4096+1024
#define NEGV -1000000000.0f
#define MIN_SCORE 0.05f
#define NMS_THR 0.6f
#define TOTAL_LOCS 174592   // 8*(16384+4096+1024+256+64)
#define WIN 512

// ---------------- device scratch ----------------
__device__ float  g_scr_scores[BATCH * SCR_STRIDE];
__device__ int    g_scr_class [BATCH * SCR_STRIDE];
__device__ float4 g_scr_boxes [BATCH * SCR_STRIDE];

__device__ float  g_pool_scores[BATCH * POOL];
__device__ int    g_pool_class [BATCH * POOL];
__device__ float4 g_pool_boxes [BATCH * POOL];

__device__ __forceinline__ float sigm(float x) { return 1.0f / (1.0f + expf(-x)); }

struct HeadPtrs {
    const float* cls[5];
    const float* reg[5];
    const float* ctr[5];
};

// ---------------- kernel A: fused decode, ONE THREAD per location --------------
__global__ __launch_bounds__(256)
void decode_all_kernel(HeadPtrs P)
{
    int t = blockIdx.x * 256 + threadIdx.x;
    if (t >= TOTAL_LOCS) return;

    int lvl, base, logN, logW; float stride;
    if      (t < 131072) { lvl=0; base=0;      logN=14; logW=7; stride=8.f;   }
    else if (t < 163840) { lvl=1; base=131072; logN=12; logW=6; stride=16.f;  }
    else if (t < 172032) { lvl=2; base=163840; logN=10; logW=5; stride=32.f;  }
    else if (t < 174080) { lvl=3; base=172032; logN=8;  logW=4; stride=64.f;  }
    else                 { lvl=4; base=174080; logN=6;  logW=3; stride=128.f; }

    int local = t - base;
    int b = local >> logN;
    int k = local & ((1 << logN) - 1);
    int N = 1 << logN;

    const float4* cp4 = (const float4*)(P.cls[lvl] + (size_t)(b * N + k) * NCLS);
    float4 q = cp4[0];
    float v0 = q.x, v1 = q.y, v2 = q.z, v3 = q.w;
    int   c0 = 0,   c1 = 1,   c2 = 2,   c3 = 3;
    #pragma unroll
    for (int j = 1; j < 20; j++) {
        float4 p = cp4[j];
        if (p.x > v0) { v0 = p.x; c0 = 4*j;     }
        if (p.y > v1) { v1 = p.y; c1 = 4*j + 1; }
        if (p.z > v2) { v2 = p.z; c2 = 4*j + 2; }
        if (p.w > v3) { v3 = p.w; c3 = 4*j + 3; }
    }
    float v = v0; int ci = c0;
    if (v1 > v || (v1 == v && c1 < ci)) { v = v1; ci = c1; }
    if (v2 > v || (v2 == v && c2 < ci)) { v = v2; ci = c2; }
    if (v3 > v || (v3 == v && c3 < ci)) { v = v3; ci = c3; }

    float ct    = P.ctr[lvl][(size_t)b * N + k];
    float score = sqrtf(sigm(v) * sigm(ct));

    const float4 r = ((const float4*)P.reg[lvl])[(size_t)b * N + k];
    float e0 = expf(r.x), e1 = expf(r.y), e2 = expf(r.z), e3 = expf(r.w);

    float px = ((k & ((1 << logW) - 1)) + 0.5f) * stride;
    float py = ((k >> logW)             + 0.5f) * stride;

    int x1 = (int)(px - e0);          // C truncation == jnp astype(int32)
    int y1 = (int)(py - e1);
    int x2 = (int)(px + e2);
    int y2 = (int)(py + e3);
    x1 = max(x1, 0);    y1 = max(y1, 0);
    x2 = min(x2, 1023); y2 = min(y2, 1023);

    float4 box = make_float4((float)x1, (float)y1, (float)x2, (float)y2);
    if (lvl < 3) {
        const int scrOff[3] = {0, 16384, 20480};
        size_t o = (size_t)b * SCR_STRIDE + scrOff[lvl] + k;
        g_scr_scores[o] = score;
        g_scr_class [o] = ci;
        g_scr_boxes [o] = box;
    } else {
        const int poolOff[2] = {3000, 3256};
        size_t o = (size_t)b * POOL + poolOff[lvl - 3] + k;
        g_pool_scores[o] = score;
        g_pool_class [o] = ci;
        g_pool_boxes [o] = box;
    }
}

// ---------------- kernel B: histogram radix-select top-1000 --------------------
#define TK_NT 1024
__global__ __launch_bounds__(TK_NT)
void topk_kernel()
{
    const int lvlN[3]    = {16384, 4096, 1024};
    const int lvlOff[3]  = {0, 16384, 20480};
    const int poolOff[3] = {0, 1000, 2000};

    int b = blockIdx.x / 3;
    int l = blockIdx.x % 3;
    int N = lvlN[l];
    size_t base  = (size_t)b * SCR_STRIDE + lvlOff[l];
    size_t pbase = (size_t)b * POOL + poolOff[l];

    extern __shared__ char tsm[];
    int* hist = (int*)tsm;                                          // 8192*4 = 32768
    unsigned long long* stash = (unsigned long long*)(tsm + 32768); // 4096*8 = 32768
    __shared__ int wsum[32], wsuf[32];
    __shared__ int s_B, s_above, s_w, s_t;
    __shared__ unsigned s_T;

    int tid = threadIdx.x, lane = tid & 31, wid = tid >> 5;

    for (int i = tid; i < 8192; i += TK_NT) hist[i] = 0;
    if (tid < 1000) g_pool_scores[pbase + tid] = NEGV;  // safety default
    if (tid == 0) { s_w = 0; s_t = 0; }
    __syncthreads();

    // pass 1: histogram of bits>>17 (scores in (0,1) -> bins < 8128)
    for (int i = tid; i < N; i += TK_NT) {
        unsigned u = __float_as_uint(g_scr_scores[base + i]);
        atomicAdd(&hist[u >> 17], 1);
    }
    __syncthreads();

    // block suffix scan over bins
    int lo_bin = tid * 8;
    int psum = 0;
    #pragma unroll
    for (int j = 0; j < 8; j++) psum += hist[lo_bin + j];
    int x = psum;
    #pragma unroll
    for (int off = 1; off < 32; off <<= 1) {
        int y = __shfl_down_sync(0xffffffffu, x, off);
        if (lane + off < 32) x += y;
    }
    if (lane == 0) wsum[wid] = x;
    __syncthreads();
    if (tid < 32) {
        int y = wsum[tid];
        #pragma unroll
        for (int off = 1; off < 32; off <<= 1) {
            int z = __shfl_down_sync(0xffffffffu, y, off);
            if (tid + off < 32) y += z;
        }
        wsuf[tid] = y;
    }
    __syncthreads();
    {
        int higher = (wid + 1 < 32) ? wsuf[wid + 1] : 0;
        int cum = higher + (x - psum);
        #pragma unroll
        for (int j = 7; j >= 0; j--) {
            int h = hist[lo_bin + j];
            if (cum < 1000 && cum + h >= 1000) { s_B = lo_bin + j; s_above = cum; }
            cum += h;
        }
    }
    __syncthreads();
    int B = s_B, above = s_above;

    // pass 2: bins > B emit; bin == B stashed
    for (int i = tid; i < N; i += TK_NT) {
        unsigned u = __float_as_uint(g_scr_scores[base + i]);
        int bin = (int)(u >> 17);
        if (bin > B) {
            int slot = atomicAdd(&s_w, 1);
            g_pool_scores[pbase + slot] = __uint_as_float(u);
            g_pool_class [pbase + slot] = g_scr_class[base + i];
            g_pool_boxes [pbase + slot] = g_scr_boxes[base + i];
        } else if (bin == B) {
            int p = atomicAdd(&s_t, 1);
            if (p < 4096) stash[p] = ((unsigned long long)u << 32) | (unsigned)i;
        }
    }
    __syncthreads();

    int M = min(s_t, 4096);
    int kneed = 1000 - above;

    // warp 0: 17-bit binary search within bin for threshold T
    if (wid == 0) {
        unsigned lo = (unsigned)B << 17, hi = ((unsigned)B << 17) | 0x1FFFFu;
        for (int it = 0; it < 17; it++) {
            unsigned d   = hi - lo;
            unsigned mid = lo + (d >> 1) + (d & 1u);
            int loc = 0;
            for (int i = lane; i < M; i += 32) loc += ((unsigned)(stash[i] >> 32) >= mid);
            #pragma unroll
            for (int off = 16; off > 0; off >>= 1)
                loc += __shfl_xor_sync(0xffffffffu, loc, off);
            if (lo < hi) {
                if (loc >= kneed) lo = mid; else hi = mid - 1u;
            }
        }
        if (lane == 0) s_T = lo;
    }
    __syncthreads();
    unsigned T = s_T;

    // emit stash strictly greater than T
    for (int i = tid; i < M; i += TK_NT) {
        if ((unsigned)(stash[i] >> 32) > T) {
            int slot = atomicAdd(&s_w, 1);
            unsigned idx = (unsigned)(stash[i] & 0xffffffffull);
            g_pool_scores[pbase + slot] = __uint_as_float((unsigned)(stash[i] >> 32));
            g_pool_class [pbase + slot] = g_scr_class[base + idx];
            g_pool_boxes [pbase + slot] = g_scr_boxes[base + idx];
        }
    }
    __syncthreads();

    // ties == T: lowest original indices first (jax.lax.top_k tie semantics); tiny
    if (tid == 0) {
        int got  = s_w;
        int need = 1000 - got;
        for (int j = 0; j < need; j++) {
            unsigned bestIdx = 0xffffffffu; int bestPos = -1;
            for (int i = 0; i < M; i++) {
                unsigned long long e = stash[i];
                if ((unsigned)(e >> 32) == T) {
                    unsigned ii = (unsigned)(e & 0xffffffffull);
                    if (ii < bestIdx) { bestIdx = ii; bestPos = i; }
                }
            }
            if (bestPos < 0) break;
            stash[bestPos] = 0;
            int slot = got + j;
            g_pool_scores[pbase + slot] = __uint_as_float(T);
            g_pool_class [pbase + slot] = g_scr_class[base + bestIdx];
            g_pool_boxes [pbase + slot] = g_scr_boxes[base + bestIdx];
        }
    }
}

// ---------------- kernel C: sort + windowed-bitmask NMS, one block per image ---
#define NMS_NT 1024
__global__ __launch_bounds__(NMS_NT)
void nms_kernel(float* __restrict__ out)
{
    int b = blockIdx.x;
    extern __shared__ char dsm[];
    unsigned long long* key = (unsigned long long*)dsm;   // 4096*8 = 32768
    unsigned* mask = (unsigned*)dsm;                      // REUSES key after gather: 512*16*4 = 32768
    short* sx1  = (short*)(dsm + 32768);                  // 3328*2 each
    short* sy1  = (short*)(dsm + 32768 + 6656);
    short* sx2  = (short*)(dsm + 32768 + 13312);
    short* sy2  = (short*)(dsm + 32768 + 19968);
    short* scls = (short*)(dsm + 32768 + 26624);          // -> 66048
    float* ssc  = (float*)(dsm + 66048);                  // 3328*4 -> 79360
    float* kx1  = (float*)(dsm + 79360);                  // kept arrays: 7*100 floats
    float* ky1  = kx1 + 100;
    float* kx2  = kx1 + 200;
    float* ky2  = kx1 + 300;
    float* kar  = kx1 + 400;
    float* ksc  = kx1 + 500;
    float* kcl  = kx1 + 600;                              // -> 82160
    unsigned char* wdead = (unsigned char*)(dsm + 82160); // 512 bytes -> 82672

    __shared__ int s_kept;

    int tid = threadIdx.x, lane = tid & 31;

    // keys: (score_bits << 32) | ~pool_index ; dead -> 0
    for (int i = tid; i < NPAD; i += NMS_NT) {
        unsigned long long k = 0ull;
        if (i < POOL) {
            float sc = g_pool_scores[(size_t)b * POOL + i];
            if (sc > MIN_SCORE)
                k = ((unsigned long long)__float_as_uint(sc) << 32) | (unsigned)(~i);
        }
        key[i] = k;
    }

    // bitonic sort descending (score desc, pool index asc on equal scores)
    for (int kk = 2; kk <= NPAD; kk <<= 1) {
        for (int jj = kk >> 1; jj > 0; jj >>= 1) {
            __syncthreads();
            for (int t = tid; t < NPAD; t += NMS_NT) {
                int ixj = t ^ jj;
                if (ixj > t) {
                    unsigned long long a = key[t], c = key[ixj];
                    bool up = ((t & kk) == 0);
                    if ((a < c) == up) { key[t] = c; key[ixj] = a; }
                }
            }
        }
    }
    __syncthreads();

    // gather sorted candidates
    for (int i = tid; i < POOL; i += NMS_NT) {
        unsigned long long k = key[i];
        if (k) {
            unsigned idx = ~(unsigned)(k & 0xffffffffull);
            ssc[i] = __uint_as_float((unsigned)(k >> 32));
            float4 f = g_pool_boxes[(size_t)b * POOL + idx];
            sx1[i] = (short)f.x; sy1[i] = (short)f.y;
            sx2[i] = (short)f.z; sy2[i] = (short)f.w;
            scls[i] = (short)g_pool_class[(size_t)b * POOL + idx];
        } else {
            ssc[i] = 0.f;
            sx1[i] = 0; sy1[i] = 0; sx2[i] = 0; sy2[i] = 0; scls[i] = 0;
        }
    }
    if (tid == 0) s_kept = 0;
    __syncthreads();   // key[] dead from here; mask[] may reuse it

    // windowed bitmask NMS. Equivalence: greedy argmax-NMS == scan sorted
    // order, keep iff IoU <= thr vs every previously-kept box.
    for (int w0 = 0; w0 < POOL; w0 += WIN) {
        if (s_kept >= 100 || ssc[w0] <= 0.f) break;      // uniform (post-barrier)
        int wlen = min(WIN, POOL - w0);

        // phase a: per-candidate dead byte vs already-kept boxes (parallel)
        for (int j = tid; j < wlen; j += NMS_NT) {
            int gj = w0 + j;
            unsigned char d = (ssc[gj] <= 0.f) ? 1 : 0;
            if (!d) {
                float x1 = sx1[gj], y1 = sy1[gj], x2 = sx2[gj], y2 = sy2[gj];
                float a = (x2 - x1) * (y2 - y1);
                int kn = s_kept;
                for (int k = 0; k < kn && !d; k++) {
                    float iw = fmaxf(fminf(x2, kx2[k]) - fmaxf(x1, kx1[k]), 0.f);
                    float ih = fmaxf(fminf(y2, ky2[k]) - fmaxf(y1, ky1[k]), 0.f);
                    float inter = iw * ih;
                    float denom = ((a + kar[k]) - inter) + 1e-12f;  // same assoc as ref
                    if (inter / denom > NMS_THR) d = 1;
                }
            }
            wdead[j] = d;
        }

        // phase b: intra-window suppression bit-matrix (parallel).
        // Row j, word w: bit l set <=> IoU(j, i) > thr for i = w*32+l with i > j
        // (i.e. candidates AFTER j in sorted order, which j suppresses if kept).
        for (int task = tid; task < wlen * 16; task += NMS_NT) {
            int j = task >> 4, w = task & 15;
            unsigned word = 0u;
            int lmin = max(0, j + 1 - w * 32);           // only i > j
            int lmax = min(32, wlen - w * 32);           // only i < wlen
            if (lmin < lmax) {
                int gj = w0 + j;
                float jx1 = sx1[gj], jy1 = sy1[gj], jx2 = sx2[gj], jy2 = sy2[gj];
                float ja = (jx2 - jx1) * (jy2 - jy1);
                for (int l = lmin; l < lmax; l++) {
                    int gi = w0 + w * 32 + l;
                    float x1 = sx1[gi], y1 = sy1[gi], x2 = sx2[gi], y2 = sy2[gi];
                    float iw = fmaxf(fminf(x2, jx2) - fmaxf(x1, jx1), 0.f);
                    float ih = fmaxf(fminf(y2, jy2) - fmaxf(y1, jy1), 0.f);
                    float inter = iw * ih;
                    float a = (x2 - x1) * (y2 - y1);
                    float denom = ((a + ja) - inter) + 1e-12f;
                    if (inter / denom > NMS_THR) word |= (1u << l);
                }
            }
            mask[j * 16 + w] = word;
        }
        __syncthreads();

        // sweep: warp 0, dead bits in registers (lane<16 holds one 32-bit word)
        if (tid < 32) {
            int kept = s_kept;
            unsigned deadw = 0u;
            for (int c0 = 0; c0 < wlen && kept < 100; c0 += 32) {
                int j0 = c0 + lane;
                bool okj = (j0 < wlen) && (wdead[j0] == 0);
                unsigned wordc = __shfl_sync(0xffffffffu, deadw, c0 >> 5);
                bool alive = okj && !((wordc >> lane) & 1u);
                unsigned m = __ballot_sync(0xffffffffu, alive);
                while (m != 0u && kept < 100) {
                    int sl = __ffs(m) - 1;
                    int j  = c0 + sl;
                    int gj = w0 + j;
                    if (lane == 0) {
                        float x1 = sx1[gj], y1 = sy1[gj], x2 = sx2[gj], y2 = sy2[gj];
                        kx1[kept] = x1; ky1[kept] = y1;
                        kx2[kept] = x2; ky2[kept] = y2;
                        kar[kept] = (x2 - x1) * (y2 - y1);
                        ksc[kept] = ssc[gj];
                        kcl[kept] = (float)scls[gj];
                    }
                    if (lane < 16) deadw |= mask[j * 16 + lane];
                    kept++;
                    wordc = __shfl_sync(0xffffffffu, deadw, c0 >> 5);
                    alive = okj && (lane > sl) && !((wordc >> lane) & 1u);
                    m = __ballot_sync(0xffffffffu, alive);
                }
            }
            if (lane == 0) s_kept = kept;
        }
        __syncthreads();
    }
    __syncthreads();

    // outputs: warp 0 owns all writes
    if (tid < 32) {
        int kc = s_kept;
        for (int j = lane; j < 100; j += 32) {
            bool ok = j < kc;
            out[b * 100 + j]       = ok ? ksc[j] : -1.f;
            out[800 + b * 100 + j] = ok ? kcl[j] : -1.f;
            float* ob = out + 1600 + ((size_t)(b * 100 + j)) * 4;
            if (ok) { ob[0] = kx1[j]; ob[1] = ky1[j]; ob[2] = kx2[j]; ob[3] = ky2[j]; }
            else    { ob[0] = ob[1] = ob[2] = ob[3] = -1.f; }
        }
    }
}

// ---------------- host launcher -------------------------------------------------
extern "C" void kernel_launch(void* const* d_in, const int* in_sizes, int n_in,
                              void* d_out, int out_size)
{
    (void)n_in; (void)out_size;

    HeadPtrs P;
    if (in_sizes[1] == 8 * 64 * 64 * NCLS) {
        for (int i = 0; i < 5; i++) {
            P.cls[i] = (const float*)d_in[i];
            P.reg[i] = (const float*)d_in[5 + i];
            P.ctr[i] = (const float*)d_in[10 + i];
        }
    } else {
        for (int i = 0; i < 5; i++) {
            P.cls[i] = (const float*)d_in[3 * i + 0];
            P.reg[i] = (const float*)d_in[3 * i + 1];
            P.ctr[i] = (const float*)d_in[3 * i + 2];
        }
    }

    decode_all_kernel<<<(TOTAL_LOCS + 255) / 256, 256>>>(P);

    cudaFuncSetAttribute(topk_kernel, cudaFuncAttributeMaxDynamicSharedMemorySize, 65536);
    topk_kernel<<<24, TK_NT, 65536>>>();

    cudaFuncSetAttribute(nms_kernel, cudaFuncAttributeMaxDynamicSharedMemorySize, 82688);
    nms_kernel<<<BATCH, NMS_NT, 82688>>>((float*)d_out);
}

// round 15
// speedup vs baseline: 1.5155x; 1.5155x over previous
#include <cuda_runtime.h>
#include <math.h>

#define BATCH 8
#define NCLS 80
#define POOL 3320           // 1000+1000+1000+256+64
#define NPAD 4096
#define SCR_STRIDE 21504    // 16384+4096+1024
#define NEGV -1000000000.0f
#define MIN_SCORE 0.05f
#define NMS_THR 0.6f
#define TOTAL_LOCS 174592   // 8*(16384+4096+1024+256+64)
#define PRESEL_K 1536       // preselect target; selected set padded-sorts into 2048

// ---------------- device scratch ----------------
__device__ float  g_scr_scores[BATCH * SCR_STRIDE];
__device__ int    g_scr_class [BATCH * SCR_STRIDE];
__device__ float4 g_scr_boxes [BATCH * SCR_STRIDE];

__device__ float  g_pool_scores[BATCH * POOL];
__device__ int    g_pool_class [BATCH * POOL];
__device__ float4 g_pool_boxes [BATCH * POOL];

__device__ __forceinline__ float sigm(float x) { return 1.0f / (1.0f + expf(-x)); }

struct HeadPtrs {
    const float* cls[5];
    const float* reg[5];
    const float* ctr[5];
};

// ---------------- kernel A: fused decode, ONE THREAD per location --------------
__global__ __launch_bounds__(256)
void decode_all_kernel(HeadPtrs P)
{
    int t = blockIdx.x * 256 + threadIdx.x;
    if (t >= TOTAL_LOCS) return;

    int lvl, base, logN, logW; float stride;
    if      (t < 131072) { lvl=0; base=0;      logN=14; logW=7; stride=8.f;   }
    else if (t < 163840) { lvl=1; base=131072; logN=12; logW=6; stride=16.f;  }
    else if (t < 172032) { lvl=2; base=163840; logN=10; logW=5; stride=32.f;  }
    else if (t < 174080) { lvl=3; base=172032; logN=8;  logW=4; stride=64.f;  }
    else                 { lvl=4; base=174080; logN=6;  logW=3; stride=128.f; }

    int local = t - base;
    int b = local >> logN;
    int k = local & ((1 << logN) - 1);
    int N = 1 << logN;

    const float4* cp4 = (const float4*)(P.cls[lvl] + (size_t)(b * N + k) * NCLS);
    float4 q = cp4[0];
    float v0 = q.x, v1 = q.y, v2 = q.z, v3 = q.w;
    int   c0 = 0,   c1 = 1,   c2 = 2,   c3 = 3;
    #pragma unroll
    for (int j = 1; j < 20; j++) {
        float4 p = cp4[j];
        if (p.x > v0) { v0 = p.x; c0 = 4*j;     }
        if (p.y > v1) { v1 = p.y; c1 = 4*j + 1; }
        if (p.z > v2) { v2 = p.z; c2 = 4*j + 2; }
        if (p.w > v3) { v3 = p.w; c3 = 4*j + 3; }
    }
    float v = v0; int ci = c0;
    if (v1 > v || (v1 == v && c1 < ci)) { v = v1; ci = c1; }
    if (v2 > v || (v2 == v && c2 < ci)) { v = v2; ci = c2; }
    if (v3 > v || (v3 == v && c3 < ci)) { v = v3; ci = c3; }

    float ct    = P.ctr[lvl][(size_t)b * N + k];
    float score = sqrtf(sigm(v) * sigm(ct));

    const float4 r = ((const float4*)P.reg[lvl])[(size_t)b * N + k];
    float e0 = expf(r.x), e1 = expf(r.y), e2 = expf(r.z), e3 = expf(r.w);

    float px = ((k & ((1 << logW) - 1)) + 0.5f) * stride;
    float py = ((k >> logW)             + 0.5f) * stride;

    int x1 = (int)(px - e0);          // C truncation == jnp astype(int32)
    int y1 = (int)(py - e1);
    int x2 = (int)(px + e2);
    int y2 = (int)(py + e3);
    x1 = max(x1, 0);    y1 = max(y1, 0);
    x2 = min(x2, 1023); y2 = min(y2, 1023);

    float4 box = make_float4((float)x1, (float)y1, (float)x2, (float)y2);
    if (lvl < 3) {
        const int scrOff[3] = {0, 16384, 20480};
        size_t o = (size_t)b * SCR_STRIDE + scrOff[lvl] + k;
        g_scr_scores[o] = score;
        g_scr_class [o] = ci;
        g_scr_boxes [o] = box;
    } else {
        const int poolOff[2] = {3000, 3256};
        size_t o = (size_t)b * POOL + poolOff[lvl - 3] + k;
        g_pool_scores[o] = score;
        g_pool_class [o] = ci;
        g_pool_boxes [o] = box;
    }
}

// ---------------- kernel B: histogram radix-select top-1000 --------------------
#define TK_NT 1024
__global__ __launch_bounds__(TK_NT)
void topk_kernel()
{
    const int lvlN[3]    = {16384, 4096, 1024};
    const int lvlOff[3]  = {0, 16384, 20480};
    const int poolOff[3] = {0, 1000, 2000};

    int b = blockIdx.x / 3;
    int l = blockIdx.x % 3;
    int N = lvlN[l];
    size_t base  = (size_t)b * SCR_STRIDE + lvlOff[l];
    size_t pbase = (size_t)b * POOL + poolOff[l];

    extern __shared__ char tsm[];
    int* hist = (int*)tsm;                                          // 8192*4 = 32768
    unsigned long long* stash = (unsigned long long*)(tsm + 32768); // 4096*8 = 32768
    __shared__ int wsum[32], wsuf[32];
    __shared__ int s_B, s_above, s_w, s_t;
    __shared__ unsigned s_T;

    int tid = threadIdx.x, lane = tid & 31, wid = tid >> 5;

    for (int i = tid; i < 8192; i += TK_NT) hist[i] = 0;
    if (tid < 1000) g_pool_scores[pbase + tid] = NEGV;  // safety default
    if (tid == 0) { s_w = 0; s_t = 0; }
    __syncthreads();

    // pass 1: histogram of bits>>17 (scores in (0,1) -> bins < 8128)
    for (int i = tid; i < N; i += TK_NT) {
        unsigned u = __float_as_uint(g_scr_scores[base + i]);
        atomicAdd(&hist[u >> 17], 1);
    }
    __syncthreads();

    // block suffix scan over bins
    int lo_bin = tid * 8;
    int psum = 0;
    #pragma unroll
    for (int j = 0; j < 8; j++) psum += hist[lo_bin + j];
    int x = psum;
    #pragma unroll
    for (int off = 1; off < 32; off <<= 1) {
        int y = __shfl_down_sync(0xffffffffu, x, off);
        if (lane + off < 32) x += y;
    }
    if (lane == 0) wsum[wid] = x;
    __syncthreads();
    if (tid < 32) {
        int y = wsum[tid];
        #pragma unroll
        for (int off = 1; off < 32; off <<= 1) {
            int z = __shfl_down_sync(0xffffffffu, y, off);
            if (tid + off < 32) y += z;
        }
        wsuf[tid] = y;
    }
    __syncthreads();
    {
        int higher = (wid + 1 < 32) ? wsuf[wid + 1] : 0;
        int cum = higher + (x - psum);
        #pragma unroll
        for (int j = 7; j >= 0; j--) {
            int h = hist[lo_bin + j];
            if (cum < 1000 && cum + h >= 1000) { s_B = lo_bin + j; s_above = cum; }
            cum += h;
        }
    }
    __syncthreads();
    int B = s_B, above = s_above;

    // pass 2: bins > B emit; bin == B stashed
    for (int i = tid; i < N; i += TK_NT) {
        unsigned u = __float_as_uint(g_scr_scores[base + i]);
        int bin = (int)(u >> 17);
        if (bin > B) {
            int slot = atomicAdd(&s_w, 1);
            g_pool_scores[pbase + slot] = __uint_as_float(u);
            g_pool_class [pbase + slot] = g_scr_class[base + i];
            g_pool_boxes [pbase + slot] = g_scr_boxes[base + i];
        } else if (bin == B) {
            int p = atomicAdd(&s_t, 1);
            if (p < 4096) stash[p] = ((unsigned long long)u << 32) | (unsigned)i;
        }
    }
    __syncthreads();

    int M = min(s_t, 4096);
    int kneed = 1000 - above;

    // warp 0: 17-bit binary search within bin for threshold T
    if (wid == 0) {
        unsigned lo = (unsigned)B << 17, hi = ((unsigned)B << 17) | 0x1FFFFu;
        for (int it = 0; it < 17; it++) {
            unsigned d   = hi - lo;
            unsigned mid = lo + (d >> 1) + (d & 1u);
            int loc = 0;
            for (int i = lane; i < M; i += 32) loc += ((unsigned)(stash[i] >> 32) >= mid);
            #pragma unroll
            for (int off = 16; off > 0; off >>= 1)
                loc += __shfl_xor_sync(0xffffffffu, loc, off);
            if (lo < hi) {
                if (loc >= kneed) lo = mid; else hi = mid - 1u;
            }
        }
        if (lane == 0) s_T = lo;
    }
    __syncthreads();
    unsigned T = s_T;

    // emit stash strictly greater than T
    for (int i = tid; i < M; i += TK_NT) {
        if ((unsigned)(stash[i] >> 32) > T) {
            int slot = atomicAdd(&s_w, 1);
            unsigned idx = (unsigned)(stash[i] & 0xffffffffull);
            g_pool_scores[pbase + slot] = __uint_as_float((unsigned)(stash[i] >> 32));
            g_pool_class [pbase + slot] = g_scr_class[base + idx];
            g_pool_boxes [pbase + slot] = g_scr_boxes[base + idx];
        }
    }
    __syncthreads();

    // ties == T: lowest original indices first (jax.lax.top_k tie semantics); tiny
    if (tid == 0) {
        int got  = s_w;
        int need = 1000 - got;
        for (int j = 0; j < need; j++) {
            unsigned bestIdx = 0xffffffffu; int bestPos = -1;
            for (int i = 0; i < M; i++) {
                unsigned long long e = stash[i];
                if ((unsigned)(e >> 32) == T) {
                    unsigned ii = (unsigned)(e & 0xffffffffull);
                    if (ii < bestIdx) { bestIdx = ii; bestPos = i; }
                }
            }
            if (bestPos < 0) break;
            stash[bestPos] = 0;
            int slot = got + j;
            g_pool_scores[pbase + slot] = __uint_as_float(T);
            g_pool_class [pbase + slot] = g_scr_class[base + bestIdx];
            g_pool_boxes [pbase + slot] = g_scr_boxes[base + bestIdx];
        }
    }
}

// ---------------- kernel C: preselect + sort + scan-kept NMS -------------------
#define NMS_NT 1024
__global__ __launch_bounds__(NMS_NT)
void nms_kernel(float* __restrict__ out)
{
    int b = blockIdx.x;
    extern __shared__ char dsm[];
    unsigned long long* key = (unsigned long long*)dsm;   // 4096*8 = 32768
    int* hist = (int*)dsm;                                // reuses key area BEFORE keys built
    short* sx1  = (short*)(dsm + 32768);                  // 3328*2 each
    short* sy1  = (short*)(dsm + 32768 + 6656);
    short* sx2  = (short*)(dsm + 32768 + 13312);
    short* sy2  = (short*)(dsm + 32768 + 19968);
    short* scls = (short*)(dsm + 32768 + 26624);          // -> 66048
    float* ssc  = (float*)(dsm + 66048);                  // 3328*4 -> 79360
    float* kx1  = (float*)(dsm + 79360);                  // kept arrays: 7*100 floats
    float* ky1  = kx1 + 100;
    float* kx2  = kx1 + 200;
    float* ky2  = kx1 + 300;
    float* kar  = kx1 + 400;
    float* ksc  = kx1 + 500;
    float* kcl  = kx1 + 600;                              // -> 82160

    __shared__ int wsum[32], wsuf[32];
    __shared__ int s_B, s_above, s_w, s_kept;

    int tid = threadIdx.x, lane = tid & 31, wid = tid >> 5;

    // ---- preselect: histogram over alive pool scores (bins = score bits >> 17)
    for (int i = tid; i < 8192; i += NMS_NT) hist[i] = 0;
    if (tid == 0) { s_B = 0; s_above = -1; }
    __syncthreads();
    for (int i = tid; i < POOL; i += NMS_NT) {
        float sc = g_pool_scores[(size_t)b * POOL + i];
        if (sc > MIN_SCORE) atomicAdd(&hist[__float_as_uint(sc) >> 17], 1);
    }
    __syncthreads();

    // suffix scan: find bin B with above(B) < PRESEL_K <= above(B)+hist[B]
    int lo_bin = tid * 8;
    int psum = 0;
    #pragma unroll
    for (int j = 0; j < 8; j++) psum += hist[lo_bin + j];
    int x = psum;
    #pragma unroll
    for (int off = 1; off < 32; off <<= 1) {
        int y = __shfl_down_sync(0xffffffffu, x, off);
        if (lane + off < 32) x += y;
    }
    if (lane == 0) wsum[wid] = x;
    __syncthreads();
    if (tid < 32) {
        int y = wsum[tid];
        #pragma unroll
        for (int off = 1; off < 32; off <<= 1) {
            int z = __shfl_down_sync(0xffffffffu, y, off);
            if (tid + off < 32) y += z;
        }
        wsuf[tid] = y;
    }
    __syncthreads();
    {
        int higher = (wid + 1 < 32) ? wsuf[wid + 1] : 0;
        int cum = higher + (x - psum);
        #pragma unroll
        for (int j = 7; j >= 0; j--) {
            int h = hist[lo_bin + j];
            if (cum < PRESEL_K && cum + h >= PRESEL_K) { s_B = lo_bin + j; s_above = cum; }
            cum += h;
        }
    }
    __syncthreads();
    int B     = s_B;
    int alive = wsuf[0];                                       // total alive candidates
    int selCount = (s_above < 0) ? alive : (s_above + hist[B]); // count in bins >= B
    // (read hist[B] before keys overwrite it; barrier below orders this)

    bool fullmode = (selCount > 2048);   // pathological tie-bin: go straight to full sort

    // ---- up to two attempts: preselected-2048 path, then full-4096 fallback ----
    int nsel = 0;
    for (int attempt = 0; attempt < 2; attempt++) {
        int len = fullmode ? NPAD : 2048;
        int lim = len < POOL ? len : POOL;
        if (tid == 0) { s_w = 0; s_kept = 0; }
        __syncthreads();

        // build keys: (score_bits << 32) | ~pool_index; selection = bins >= B
        // (selected set is an exact prefix of the full descending sort order)
        for (int i = tid; i < POOL; i += NMS_NT) {
            float sc = g_pool_scores[(size_t)b * POOL + i];
            if (sc > MIN_SCORE) {
                unsigned u = __float_as_uint(sc);
                if (fullmode || (int)(u >> 17) >= B) {
                    int slot = atomicAdd(&s_w, 1);
                    key[slot] = ((unsigned long long)u << 32) | (unsigned)(~i);
                }
            }
        }
        __syncthreads();
        nsel = s_w;
        for (int i = tid; i < len; i += NMS_NT)
            if (i >= nsel) key[i] = 0ull;
        // bitonic sort descending (score desc, pool index asc on equal scores)
        for (int kk = 2; kk <= len; kk <<= 1) {
            for (int jj = kk >> 1; jj > 0; jj >>= 1) {
                __syncthreads();
                for (int t = tid; t < len; t += NMS_NT) {
                    int ixj = t ^ jj;
                    if (ixj > t) {
                        unsigned long long a = key[t], c = key[ixj];
                        bool up = ((t & kk) == 0);
                        if ((a < c) == up) { key[t] = c; key[ixj] = a; }
                    }
                }
            }
        }
        __syncthreads();

        // gather sorted candidates
        for (int i = tid; i < lim; i += NMS_NT) {
            unsigned long long k = key[i];
            if (k) {
                unsigned idx = ~(unsigned)(k & 0xffffffffull);
                ssc[i] = __uint_as_float((unsigned)(k >> 32));
                float4 f = g_pool_boxes[(size_t)b * POOL + idx];
                sx1[i] = (short)f.x; sy1[i] = (short)f.y;
                sx2[i] = (short)f.z; sy2[i] = (short)f.w;
                scls[i] = (short)g_pool_class[(size_t)b * POOL + idx];
            } else {
                ssc[i] = 0.f;
            }
        }
        __syncthreads();

        // scan-kept greedy NMS: warp 0 only, broadcasts via shared + __syncwarp.
        // Equivalence: greedy argmax-NMS == scan sorted order, keep iff
        // IoU <= thr vs every previously-kept box.
        if (tid < 32) {
            int kept = 0;
            for (int base0 = 0; base0 < lim && kept < 100; base0 += 32) {
                if (ssc[base0] <= 0.f) break;          // sorted: all dead from here
                int i = base0 + lane;
                bool al = (i < lim) && (ssc[i] > 0.f);
                float x1 = 0, y1 = 0, x2 = 0, y2 = 0, a = 0;
                if (al) {
                    x1 = sx1[i]; y1 = sy1[i]; x2 = sx2[i]; y2 = sy2[i];
                    a = (x2 - x1) * (y2 - y1);
                    #pragma unroll 1
                    for (int k = 0; k < kept && al; k++) {
                        float iw = fmaxf(fminf(x2, kx2[k]) - fmaxf(x1, kx1[k]), 0.f);
                        float ih = fmaxf(fminf(y2, ky2[k]) - fmaxf(y1, ky1[k]), 0.f);
                        float inter = iw * ih;
                        float denom = ((a + kar[k]) - inter) + 1e-12f; // same assoc as ref
                        if (inter / denom > NMS_THR) al = false;
                    }
                }
                unsigned m = __ballot_sync(0xffffffffu, al);
                while (m != 0u && kept < 100) {
                    int sl = __ffs(m) - 1;
                    if (lane == sl) {
                        kx1[kept] = x1; ky1[kept] = y1;
                        kx2[kept] = x2; ky2[kept] = y2;
                        kar[kept] = a;
                        ksc[kept] = ssc[i];
                        kcl[kept] = (float)scls[i];
                        al = false;
                    }
                    __syncwarp();
                    float rx1 = kx1[kept], ry1 = ky1[kept];
                    float rx2 = kx2[kept], ry2 = ky2[kept], ra = kar[kept];
                    kept++;
                    if (al && lane > sl) {
                        float iw = fmaxf(fminf(x2, rx2) - fmaxf(x1, rx1), 0.f);
                        float ih = fmaxf(fminf(y2, ry2) - fmaxf(y1, ry1), 0.f);
                        float inter = iw * ih;
                        float denom = ((a + ra) - inter) + 1e-12f;
                        if (inter / denom > NMS_THR) al = false;
                    }
                    m = __ballot_sync(0xffffffffu, al);
                }
            }
            if (lane == 0) s_kept = kept;
        }
        __syncthreads();

        // retry with full sort only if we ran out of preselected candidates
        // while real candidates were excluded (correctness guarantee).
        bool need_retry = (!fullmode) && (s_kept < 100) && (alive > nsel);
        if (!need_retry) break;
        fullmode = true;
        __syncthreads();
    }

    // outputs: warp 0 owns all writes
    if (tid < 32) {
        int kc = s_kept;
        for (int j = lane; j < 100; j += 32) {
            bool ok = j < kc;
            out[b * 100 + j]       = ok ? ksc[j] : -1.f;
            out[800 + b * 100 + j] = ok ? kcl[j] : -1.f;
            float* ob = out + 1600 + ((size_t)(b * 100 + j)) * 4;
            if (ok) { ob[0] = kx1[j]; ob[1] = ky1[j]; ob[2] = kx2[j]; ob[3] = ky2[j]; }
            else    { ob[0] = ob[1] = ob[2] = ob[3] = -1.f; }
        }
    }
}

// ---------------- host launcher -------------------------------------------------
extern "C" void kernel_launch(void* const* d_in, const int* in_sizes, int n_in,
                              void* d_out, int out_size)
{
    (void)n_in; (void)out_size;

    HeadPtrs P;
    if (in_sizes[1] == 8 * 64 * 64 * NCLS) {
        for (int i = 0; i < 5; i++) {
            P.cls[i] = (const float*)d_in[i];
            P.reg[i] = (const float*)d_in[5 + i];
            P.ctr[i] = (const float*)d_in[10 + i];
        }
    } else {
        for (int i = 0; i < 5; i++) {
            P.cls[i] = (const float*)d_in[3 * i + 0];
            P.reg[i] = (const float*)d_in[3 * i + 1];
            P.ctr[i] = (const float*)d_in[3 * i + 2];
        }
    }

    decode_all_kernel<<<(TOTAL_LOCS + 255) / 256, 256>>>(P);

    cudaFuncSetAttribute(topk_kernel, cudaFuncAttributeMaxDynamicSharedMemorySize, 65536);
    topk_kernel<<<24, TK_NT, 65536>>>();

    cudaFuncSetAttribute(nms_kernel, cudaFuncAttributeMaxDynamicSharedMemorySize, 82176);
    nms_kernel<<<BATCH, NMS_NT, 82176>>>((float*)d_out);
}